// round 2
// baseline (speedup 1.0000x reference)
#include <cuda_runtime.h>
#include <math.h>

#define BATCH 8
#define C 128
#define NN 4096          // H*W = 64*64
#define D 16             // q/k head dim
#define G 32             // groups
#define CPG (C / G)      // 4 channels per group
#define QM 128           // query tile
#define KT 32            // key tile
#define EPS 1e-5f

typedef unsigned long long u64;

// ---------------- f32x2 packed-math helpers ----------------------------------
__device__ __forceinline__ u64 pack2(float x, float y) {
    u64 r; asm("mov.b64 %0,{%1,%2};" : "=l"(r) : "f"(x), "f"(y)); return r;
}
__device__ __forceinline__ float2 unpack2(u64 v) {
    float2 f; asm("mov.b64 {%0,%1},%2;" : "=f"(f.x), "=f"(f.y) : "l"(v)); return f;
}
__device__ __forceinline__ u64 fma2(u64 a, u64 b, u64 c) {
    u64 d; asm("fma.rn.f32x2 %0,%1,%2,%3;" : "=l"(d) : "l"(a), "l"(b), "l"(c)); return d;
}
__device__ __forceinline__ u64 mul2(u64 a, u64 b) {
    u64 d; asm("mul.rn.f32x2 %0,%1,%2;" : "=l"(d) : "l"(a), "l"(b)); return d;
}

// ---------------- scratch ----------------------------------------------------
__device__ float g_h[BATCH * C * NN];   // group-normed activations [B,C,N]
__device__ float g_q[BATCH * D * NN];   // q [B,D,N]
__device__ float g_k[BATCH * D * NN];   // k [B,D,N]
__device__ float g_v[BATCH * C * NN];   // v [B,C,N]
__device__ float g_a[BATCH * C * NN];   // attn output [B,C,N]

// ---------------- GroupNorm --------------------------------------------------
__global__ __launch_bounds__(256) void gn_kernel(
    const float* __restrict__ x, const float* __restrict__ w,
    const float* __restrict__ bvec, float* __restrict__ h)
{
    const int b = blockIdx.x >> 5;
    const int g = blockIdx.x & 31;
    const int c0 = g * CPG;
    const float* xp = x + ((size_t)b * C + c0) * NN;
    float* hp = h + ((size_t)b * C + c0) * NN;

    const int TOT = CPG * NN;   // 16384
    float s = 0.f, s2 = 0.f;
    for (int idx = threadIdx.x; idx < TOT; idx += 256) {
        float v = xp[idx];
        s += v; s2 += v * v;
    }
    __shared__ float red[16];
    int lane = threadIdx.x & 31, wid = threadIdx.x >> 5;
    #pragma unroll
    for (int o = 16; o > 0; o >>= 1) {
        s  += __shfl_xor_sync(0xffffffffu, s,  o);
        s2 += __shfl_xor_sync(0xffffffffu, s2, o);
    }
    if (lane == 0) { red[wid] = s; red[8 + wid] = s2; }
    __syncthreads();
    if (wid == 0) {
        float a = (lane < 8) ? red[lane] : 0.f;
        float a2 = (lane < 8) ? red[8 + lane] : 0.f;
        #pragma unroll
        for (int o = 4; o > 0; o >>= 1) {
            a  += __shfl_xor_sync(0xffffffffu, a,  o);
            a2 += __shfl_xor_sync(0xffffffffu, a2, o);
        }
        if (lane == 0) { red[0] = a; red[1] = a2; }
    }
    __syncthreads();
    const float inv_n = 1.f / (float)TOT;
    float mean = red[0] * inv_n;
    float var = red[1] * inv_n - mean * mean;
    float inv = rsqrtf(var + EPS);

    for (int idx = threadIdx.x; idx < TOT; idx += 256) {
        int c = idx >> 12;
        float v = (xp[idx] - mean) * inv;
        hp[idx] = v * w[c0 + c] + bvec[c0 + c];
    }
}

// ---------------- channel matmul (f32x2: 2 spatial columns per thread) -------
// out[b,e,n] = sum_c W[e,c]*in[b,c,n] + bias[e]  (+x residual if ADDX)
template <int E, int EPT, bool ADDX>
__global__ __launch_bounds__(256) void chanmm2_kernel(
    const float* __restrict__ W, const float* __restrict__ bias,
    const float* __restrict__ in, const float* __restrict__ xres,
    float* __restrict__ out)
{
    __shared__ u64 wd[EPT][C];          // weights pre-duplicated {w,w}
    const int e0 = blockIdx.y * EPT;
    const int b = blockIdx.z;

    for (int idx = threadIdx.x; idx < EPT * C; idx += 256) {
        int e = idx >> 7, c = idx & 127;
        float w = W[(e0 + e) * C + c];
        wd[e][c] = pack2(w, w);
    }
    __syncthreads();

    const int n0 = (blockIdx.x * 256 + threadIdx.x) * 2;
    u64 acc[EPT];
    #pragma unroll
    for (int e = 0; e < EPT; e++) {
        float bv = bias[e0 + e];
        acc[e] = pack2(bv, bv);
    }

    const float* ip = in + (size_t)b * C * NN + n0;
    #pragma unroll 4
    for (int c = 0; c < C; c++) {
        u64 hv = *(const u64*)(ip + (size_t)c * NN);
        #pragma unroll
        for (int e = 0; e < EPT; e++) acc[e] = fma2(wd[e][c], hv, acc[e]);
    }
    #pragma unroll
    for (int e = 0; e < EPT; e++) {
        float2 f = unpack2(acc[e]);
        if (ADDX) {
            float2 xr = *(const float2*)&xres[((size_t)b * C + e0 + e) * NN + n0];
            f.x += xr.x; f.y += xr.y;
        }
        *(float2*)&out[((size_t)b * E + e0 + e) * NN + n0] = f;
    }
}

// ---------------- flash attention (f32x2 packed) -----------------------------
// Per block: batch b, 128-query tile, online softmax over 4096 keys, KT=32.
// Each thread: 8 query rows x 8 v-channels (4 channel-pair u64 accumulators).
__global__ __launch_bounds__(256) void flash_kernel(
    const float* __restrict__ gq, const float* __restrict__ gk,
    const float* __restrict__ gv, float* __restrict__ ga)
{
    const int b = blockIdx.x >> 5;
    const int q0 = (blockIdx.x & 31) * QM;
    const int t = threadIdx.x;

    extern __shared__ char sm[];
    float (*q_s)[D + 1] = (float(*)[D + 1])(sm);                  // 8704 B
    float (*k_s)[KT]    = (float(*)[KT])(sm + 8704);              // 2048 B
    float (*v_s)[C + 4] = (float(*)[C + 4])(sm + 10752);          // 16896 B
    float2 (*p2)[KT + 1] = (float2(*)[KT + 1])(sm + 27648);       // 33792 B
    float* m_s  = (float*)(sm + 61440);                           // 512 B
    float* l_s  = m_s + QM;
    float* al_s = l_s + QM;

    // load Q tile, pre-scaled by 1/sqrt(D) = 0.25
    for (int idx = t; idx < QM * D; idx += 256) {
        int d = idx >> 7, i = idx & 127;
        q_s[i][d] = gq[((size_t)b * D + d) * NN + q0 + i] * 0.25f;
    }
    if (t < QM) { m_s[t] = -1e30f; l_s[t] = 0.f; }

    u64 o[8][4];
    #pragma unroll
    for (int r = 0; r < 8; r++)
        #pragma unroll
        for (int m = 0; m < 4; m++) o[r][m] = 0ull;

    const int ty = t >> 4, tx = t & 15;
    const int i0 = ty * 8, c0 = tx * 8;
    const int irow = t >> 1, half = t & 1;

    __syncthreads();

    for (int j0 = 0; j0 < NN; j0 += KT) {
        // K tile: k_s[d][j]
        for (int idx = t; idx < D * KT; idx += 256) {
            int d = idx >> 5, j = idx & 31;
            k_s[d][j] = gk[((size_t)b * D + d) * NN + j0 + j];
        }
        // V tile: v_s[j][c]
        for (int idx = t; idx < C * KT; idx += 256) {
            int c = idx >> 5, j = idx & 31;
            v_s[j][c] = gv[((size_t)b * C + c) * NN + j0 + j];
        }
        __syncthreads();

        // ---- scores (row irow, 16 cols at half*16), packed in f32x2 pairs
        u64 s2[8];
        #pragma unroll
        for (int m = 0; m < 8; m++) s2[m] = 0ull;
        #pragma unroll
        for (int d = 0; d < D; d++) {
            float qd = q_s[irow][d];
            u64 q2 = pack2(qd, qd);
            const u64* kp = (const u64*)&k_s[d][half * 16];
            #pragma unroll
            for (int m = 0; m < 8; m++) s2[m] = fma2(q2, kp[m], s2[m]);
        }
        float sv[16];
        #pragma unroll
        for (int m = 0; m < 8; m++) {
            float2 f = unpack2(s2[m]);
            sv[2 * m] = f.x; sv[2 * m + 1] = f.y;
        }
        float mx = sv[0];
        #pragma unroll
        for (int jj = 1; jj < 16; jj++) mx = fmaxf(mx, sv[jj]);
        mx = fmaxf(mx, __shfl_xor_sync(0xffffffffu, mx, 1));
        float m_old = m_s[irow];
        float m_new = fmaxf(m_old, mx);
        float sum = 0.f;
        #pragma unroll
        for (int jj = 0; jj < 16; jj++) {
            float p = __expf(sv[jj] - m_new);
            p2[irow][half * 16 + jj] = make_float2(p, p);   // pre-duplicated
            sum += p;
        }
        sum += __shfl_xor_sync(0xffffffffu, sum, 1);
        if (half == 0) {
            float al = __expf(m_old - m_new);
            al_s[irow] = al;
            l_s[irow] = l_s[irow] * al + sum;
            m_s[irow] = m_new;
        }
        __syncthreads();

        // ---- rescale + P*V accumulate (packed)
        #pragma unroll
        for (int r = 0; r < 8; r++) {
            float al = al_s[i0 + r];
            u64 a2 = pack2(al, al);
            #pragma unroll
            for (int m = 0; m < 4; m++) o[r][m] = mul2(o[r][m], a2);
        }
        #pragma unroll 4
        for (int j = 0; j < KT; j++) {
            const ulonglong2* vp = (const ulonglong2*)&v_s[j][c0];
            ulonglong2 vA = vp[0];   // channels c0+0..3 as two pairs
            ulonglong2 vB = vp[1];   // channels c0+4..7
            #pragma unroll
            for (int r = 0; r < 8; r++) {
                u64 pp = *(const u64*)&p2[i0 + r][j];
                o[r][0] = fma2(pp, vA.x, o[r][0]);
                o[r][1] = fma2(pp, vA.y, o[r][1]);
                o[r][2] = fma2(pp, vB.x, o[r][2]);
                o[r][3] = fma2(pp, vB.y, o[r][3]);
            }
        }
        __syncthreads();
    }

    // epilogue: normalize, register-transpose, coalesced float4 stores along n
    float invl[8];
    #pragma unroll
    for (int r = 0; r < 8; r++) invl[r] = 1.f / l_s[i0 + r];

    #pragma unroll
    for (int m = 0; m < 4; m++) {
        float a0[8], a1[8];
        #pragma unroll
        for (int r = 0; r < 8; r++) {
            float2 f = unpack2(o[r][m]);
            a0[r] = f.x * invl[r];
            a1[r] = f.y * invl[r];
        }
        int ch = c0 + 2 * m;
        float* b0 = &ga[((size_t)b * C + ch) * NN + q0 + i0];
        float* b1 = &ga[((size_t)b * C + ch + 1) * NN + q0 + i0];
        *(float4*)(b0)     = make_float4(a0[0], a0[1], a0[2], a0[3]);
        *(float4*)(b0 + 4) = make_float4(a0[4], a0[5], a0[6], a0[7]);
        *(float4*)(b1)     = make_float4(a1[0], a1[1], a1[2], a1[3]);
        *(float4*)(b1 + 4) = make_float4(a1[4], a1[5], a1[6], a1[7]);
    }
}

#define SMEM_FLASH 62976

// ---------------- launch -----------------------------------------------------
extern "C" void kernel_launch(void* const* d_in, const int* in_sizes, int n_in,
                              void* d_out, int out_size)
{
    const float* x    = (const float*)d_in[0];
    const float* gn_w = (const float*)d_in[1];
    const float* gn_b = (const float*)d_in[2];
    const float* q_w  = (const float*)d_in[3];
    const float* q_b  = (const float*)d_in[4];
    const float* k_w  = (const float*)d_in[5];
    const float* k_b  = (const float*)d_in[6];
    const float* v_w  = (const float*)d_in[7];
    const float* v_b  = (const float*)d_in[8];
    const float* p_w  = (const float*)d_in[9];
    const float* p_b  = (const float*)d_in[10];
    float* out = (float*)d_out;

    float *h, *q, *k, *v, *a;
    cudaGetSymbolAddress((void**)&h, g_h);
    cudaGetSymbolAddress((void**)&q, g_q);
    cudaGetSymbolAddress((void**)&k, g_k);
    cudaGetSymbolAddress((void**)&v, g_v);
    cudaGetSymbolAddress((void**)&a, g_a);

    cudaFuncSetAttribute(flash_kernel,
                         cudaFuncAttributeMaxDynamicSharedMemorySize, SMEM_FLASH);

    // 1. GroupNorm
    gn_kernel<<<BATCH * G, 256>>>(x, gn_w, gn_b, h);

    // 2. q, k, v projections (1x1 convs)
    chanmm2_kernel<D, 8, false><<<dim3(NN / 512, D / 8, BATCH), 256>>>(q_w, q_b, h, nullptr, q);
    chanmm2_kernel<D, 8, false><<<dim3(NN / 512, D / 8, BATCH), 256>>>(k_w, k_b, h, nullptr, k);
    chanmm2_kernel<C, 8, false><<<dim3(NN / 512, C / 8, BATCH), 256>>>(v_w, v_b, h, nullptr, v);

    // 3. attention (flash, online softmax, f32x2)
    flash_kernel<<<BATCH * (NN / QM), 256, SMEM_FLASH>>>(q, k, v, a);

    // 4. output projection + residual
    chanmm2_kernel<C, 8, true><<<dim3(NN / 512, C / 8, BATCH), 256>>>(p_w, p_b, a, x, out);
}

// round 4
// speedup vs baseline: 6.6192x; 6.6192x over previous
#include <cuda_runtime.h>
#include <cuda_bf16.h>
#include <cstdint>
#include <math.h>

#define BATCH 8
#define C 128
#define NN 4096
#define D 16
#define G 32
#define CPG (C / G)
#define EPS 1e-5f

typedef unsigned long long u64;

// ---------------- f32x2 helpers (projection kernels) -------------------------
__device__ __forceinline__ u64 pack2(float x, float y) {
    u64 r; asm("mov.b64 %0,{%1,%2};" : "=l"(r) : "f"(x), "f"(y)); return r;
}
__device__ __forceinline__ float2 unpack2(u64 v) {
    float2 f; asm("mov.b64 {%0,%1},%2;" : "=f"(f.x), "=f"(f.y) : "l"(v)); return f;
}
__device__ __forceinline__ u64 fma2(u64 a, u64 b, u64 c) {
    u64 d; asm("fma.rn.f32x2 %0,%1,%2,%3;" : "=l"(d) : "l"(a), "l"(b), "l"(c)); return d;
}

// ---------------- scratch ----------------------------------------------------
__device__ float          g_h [BATCH * C * NN];   // group-normed [B,C,N]
__device__ float          g_qt[BATCH * NN * D];   // q [B,N,16] (pre-scaled)
__device__ float          g_kt[BATCH * NN * D];   // k [B,N,16]
__device__ __nv_bfloat16  g_v [BATCH * C * NN];   // v [B,C,N] bf16

// ---------------- GroupNorm --------------------------------------------------
__global__ __launch_bounds__(256) void gn_kernel(
    const float* __restrict__ x, const float* __restrict__ w,
    const float* __restrict__ bvec, float* __restrict__ h)
{
    const int b = blockIdx.x >> 5;
    const int g = blockIdx.x & 31;
    const int c0 = g * CPG;
    const float* xp = x + ((size_t)b * C + c0) * NN;
    float* hp = h + ((size_t)b * C + c0) * NN;

    const int TOT = CPG * NN;
    float s = 0.f, s2 = 0.f;
    for (int idx = threadIdx.x; idx < TOT; idx += 256) {
        float v = xp[idx];
        s += v; s2 += v * v;
    }
    __shared__ float red[16];
    int lane = threadIdx.x & 31, wid = threadIdx.x >> 5;
    #pragma unroll
    for (int o = 16; o > 0; o >>= 1) {
        s  += __shfl_xor_sync(0xffffffffu, s,  o);
        s2 += __shfl_xor_sync(0xffffffffu, s2, o);
    }
    if (lane == 0) { red[wid] = s; red[8 + wid] = s2; }
    __syncthreads();
    if (wid == 0) {
        float a = (lane < 8) ? red[lane] : 0.f;
        float a2 = (lane < 8) ? red[8 + lane] : 0.f;
        #pragma unroll
        for (int o = 4; o > 0; o >>= 1) {
            a  += __shfl_xor_sync(0xffffffffu, a,  o);
            a2 += __shfl_xor_sync(0xffffffffu, a2, o);
        }
        if (lane == 0) { red[0] = a; red[1] = a2; }
    }
    __syncthreads();
    const float inv_n = 1.f / (float)TOT;
    float mean = red[0] * inv_n;
    float var = red[1] * inv_n - mean * mean;
    float inv = rsqrtf(var + EPS);
    for (int idx = threadIdx.x; idx < TOT; idx += 256) {
        int c = idx >> 12;
        float v = (xp[idx] - mean) * inv;
        hp[idx] = v * w[c0 + c] + bvec[c0 + c];
    }
}

// ---------------- q/k projection -> [b][n][16], optional scale ---------------
__global__ __launch_bounds__(256) void qk_proj_kernel(
    const float* __restrict__ W, const float* __restrict__ bias,
    const float* __restrict__ in, float* __restrict__ outt, float scale)
{
    __shared__ u64 wd[D][C];
    const int b = blockIdx.z;
    for (int idx = threadIdx.x; idx < D * C; idx += 256) {
        int e = idx >> 7, c = idx & 127;
        float w = W[e * C + c];
        wd[e][c] = pack2(w, w);
    }
    __syncthreads();
    const int n0 = (blockIdx.x * 256 + threadIdx.x) * 2;
    u64 acc[D];
    #pragma unroll
    for (int e = 0; e < D; e++) { float bv = bias[e]; acc[e] = pack2(bv, bv); }
    const float* ip = in + (size_t)b * C * NN + n0;
    #pragma unroll 4
    for (int c = 0; c < C; c++) {
        u64 hv = *(const u64*)(ip + (size_t)c * NN);
        #pragma unroll
        for (int e = 0; e < D; e++) acc[e] = fma2(wd[e][c], hv, acc[e]);
    }
    float r0[D], r1[D];
    #pragma unroll
    for (int e = 0; e < D; e++) {
        float2 f = unpack2(acc[e]);
        r0[e] = f.x * scale; r1[e] = f.y * scale;
    }
    float* o0 = outt + ((size_t)b * NN + n0) * D;
    #pragma unroll
    for (int m = 0; m < 4; m++) {
        *(float4*)(o0 + 4 * m)     = make_float4(r0[4*m], r0[4*m+1], r0[4*m+2], r0[4*m+3]);
        *(float4*)(o0 + D + 4 * m) = make_float4(r1[4*m], r1[4*m+1], r1[4*m+2], r1[4*m+3]);
    }
}

// ---------------- v projection -> bf16 [b][c][n] -----------------------------
__global__ __launch_bounds__(256) void vproj_kernel(
    const float* __restrict__ W, const float* __restrict__ bias,
    const float* __restrict__ in, __nv_bfloat16* __restrict__ out)
{
    __shared__ u64 wd[8][C];
    const int e0 = blockIdx.y * 8;
    const int b = blockIdx.z;
    for (int idx = threadIdx.x; idx < 8 * C; idx += 256) {
        int e = idx >> 7, c = idx & 127;
        float w = W[(e0 + e) * C + c];
        wd[e][c] = pack2(w, w);
    }
    __syncthreads();
    const int n0 = (blockIdx.x * 256 + threadIdx.x) * 2;
    u64 acc[8];
    #pragma unroll
    for (int e = 0; e < 8; e++) { float bv = bias[e0 + e]; acc[e] = pack2(bv, bv); }
    const float* ip = in + (size_t)b * C * NN + n0;
    #pragma unroll 4
    for (int c = 0; c < C; c++) {
        u64 hv = *(const u64*)(ip + (size_t)c * NN);
        #pragma unroll
        for (int e = 0; e < 8; e++) acc[e] = fma2(wd[e][c], hv, acc[e]);
    }
    #pragma unroll
    for (int e = 0; e < 8; e++) {
        float2 f = unpack2(acc[e]);
        __nv_bfloat162 bf;
        bf.x = __float2bfloat16_rn(f.x);
        bf.y = __float2bfloat16_rn(f.y);
        *(__nv_bfloat162*)&out[((size_t)b * C + e0 + e) * NN + n0] = bf;
    }
}

// ============================================================================
//        flash attention: mma.sync (tf32 S, bf16 PV) + fused tf32 proj
// ============================================================================
// smem layout (bytes):
#define OFF_Q   0        // f32 [128][20]   10240
#define OFF_K0  10240    // f32 [128][20]   10240
#define OFF_K1  20480
#define OFF_V0  30720    // bf16 [128][136] 34816  (272B rows)
#define OFF_V1  65536
#define OFF_PW  100352   // f32 [128][132]  67584  (later: stage [128][132])
#define SMEM_FL 167936

__device__ __forceinline__ uint32_t smem_u32(const void* p) {
    uint32_t a;
    asm("{ .reg .u64 t; cvta.to.shared.u64 t, %1; cvt.u32.u64 %0, t; }" : "=r"(a) : "l"(p));
    return a;
}
__device__ __forceinline__ void cpa16(uint32_t s, const void* g) {
    asm volatile("cp.async.cg.shared.global [%0], [%1], 16;" :: "r"(s), "l"(g));
}
#define CP_COMMIT() asm volatile("cp.async.commit_group;" ::: "memory")
#define CP_WAIT1()  asm volatile("cp.async.wait_group 1;" ::: "memory")
#define CP_WAIT0()  asm volatile("cp.async.wait_group 0;" ::: "memory")

__device__ __forceinline__ uint32_t f2tf(float f) {
    uint32_t u; asm("cvt.rna.tf32.f32 %0, %1;" : "=r"(u) : "f"(f)); return u;
}
__device__ __forceinline__ uint32_t bf2(float hi, float lo) {   // lo in low half
    uint32_t r; asm("cvt.rn.bf16x2.f32 %0, %1, %2;" : "=r"(r) : "f"(hi), "f"(lo)); return r;
}
__device__ __forceinline__ void mma_tf32(float* c, const uint32_t* a,
                                         uint32_t b0, uint32_t b1) {
    asm volatile(
        "mma.sync.aligned.m16n8k8.row.col.f32.tf32.tf32.f32 "
        "{%0,%1,%2,%3},{%4,%5,%6,%7},{%8,%9},{%0,%1,%2,%3};"
        : "+f"(c[0]), "+f"(c[1]), "+f"(c[2]), "+f"(c[3])
        : "r"(a[0]), "r"(a[1]), "r"(a[2]), "r"(a[3]), "r"(b0), "r"(b1));
}
__device__ __forceinline__ void mma_bf16(float* c, uint32_t a0, uint32_t a1,
                                         uint32_t a2, uint32_t a3,
                                         uint32_t b0, uint32_t b1) {
    asm volatile(
        "mma.sync.aligned.m16n8k16.row.col.f32.bf16.bf16.f32 "
        "{%0,%1,%2,%3},{%4,%5,%6,%7},{%8,%9},{%0,%1,%2,%3};"
        : "+f"(c[0]), "+f"(c[1]), "+f"(c[2]), "+f"(c[3])
        : "r"(a0), "r"(a1), "r"(a2), "r"(a3), "r"(b0), "r"(b1));
}
__device__ __forceinline__ void ldm4(uint32_t& r0, uint32_t& r1, uint32_t& r2,
                                     uint32_t& r3, uint32_t addr) {
    asm volatile("ldmatrix.sync.aligned.m8n8.x4.shared.b16 {%0,%1,%2,%3}, [%4];"
                 : "=r"(r0), "=r"(r1), "=r"(r2), "=r"(r3) : "r"(addr));
}

__device__ __forceinline__ void issue_tile(uint32_t sb, int buf,
    const float* __restrict__ kt, const __nv_bfloat16* __restrict__ vb,
    int b, int j0, int tid)
{
    uint32_t kdst = sb + (buf ? OFF_K1 : OFF_K0);
    #pragma unroll
    for (int u = tid; u < 512; u += 256) {
        int row = u >> 2, cc = u & 3;
        cpa16(kdst + row * 80 + cc * 16,
              kt + ((size_t)(b * NN + j0 + row)) * D + cc * 4);
    }
    uint32_t vdst = sb + (buf ? OFF_V1 : OFF_V0);
    #pragma unroll
    for (int u = tid; u < 2048; u += 256) {
        int c = u >> 4, cc = u & 15;
        cpa16(vdst + c * 272 + cc * 16,
              vb + ((size_t)(b * C + c)) * NN + j0 + cc * 8);
    }
}

__global__ __launch_bounds__(256, 1) void flash_mma_kernel(
    const float* __restrict__ qt, const float* __restrict__ kt,
    const __nv_bfloat16* __restrict__ vb, const float* __restrict__ pw,
    const float* __restrict__ pb, const float* __restrict__ x,
    float* __restrict__ out)
{
    extern __shared__ char sm[];
    const uint32_t sb = smem_u32(sm);
    const int tid = threadIdx.x;
    const int w = tid >> 5;            // 8 warps, warp w owns q rows 16w..16w+15
    const int lane = tid & 31;
    const int g = lane >> 2, t = lane & 3;
    const int b = blockIdx.x >> 5;
    const int q0 = (blockIdx.x & 31) * 128;

    // ldmatrix per-lane address offset within a V tile
    const int rowsel = (lane & 7) + ((lane >> 4) << 3);
    const int ksel = (lane >> 3) & 1;
    const uint32_t vlane = (uint32_t)(rowsel * 272 + ksel * 16);

    // prologue: Q + tile 0 + p_w loads (one group)
    #pragma unroll
    for (int u = tid; u < 512; u += 256) {
        int row = u >> 2, cc = u & 3;
        cpa16(sb + OFF_Q + row * 80 + cc * 16,
              qt + ((size_t)(b * NN + q0 + row)) * D + cc * 4);
    }
    issue_tile(sb, 0, kt, vb, b, 0, tid);
    #pragma unroll
    for (int u = tid; u < 4096; u += 256) {   // p_w f32 [e][c] -> [128][132]
        int e = u >> 5, cc = u & 31;
        cpa16(sb + OFF_PW + e * 528 + cc * 16, pw + (size_t)e * C + cc * 4);
    }
    CP_COMMIT();

    const float* sQ = (const float*)(sm + OFF_Q);
    uint32_t qa[2][4];
    float o[16][4];
    #pragma unroll
    for (int nb = 0; nb < 16; nb++)
        #pragma unroll
        for (int i = 0; i < 4; i++) o[nb][i] = 0.f;
    float rs0 = 0.f, rs1 = 0.f;

    for (int tt = 0; tt < 32; tt++) {
        const int buf = tt & 1;
        if (tt < 31) {
            issue_tile(sb, buf ^ 1, kt, vb, b, (tt + 1) * 128, tid);
            CP_COMMIT();
            CP_WAIT1();
        } else {
            CP_WAIT0();
        }
        __syncthreads();

        if (tt == 0) {   // Q fragments (tf32), once
            #pragma unroll
            for (int kc = 0; kc < 2; kc++) {
                qa[kc][0] = f2tf(sQ[(16*w + g    ) * 20 + 8*kc + t    ]);
                qa[kc][1] = f2tf(sQ[(16*w + g + 8) * 20 + 8*kc + t    ]);
                qa[kc][2] = f2tf(sQ[(16*w + g    ) * 20 + 8*kc + t + 4]);
                qa[kc][3] = f2tf(sQ[(16*w + g + 8) * 20 + 8*kc + t + 4]);
            }
        }

        const float* sK = (const float*)(sm + (buf ? OFF_K1 : OFF_K0));
        const uint32_t vbase = sb + (buf ? OFF_V1 : OFF_V0);

        // ---- S = Q K^T (tf32), 16 j-blocks
        float sc[16][4];
        #pragma unroll
        for (int nb = 0; nb < 16; nb++) {
            #pragma unroll
            for (int i = 0; i < 4; i++) sc[nb][i] = 0.f;
            #pragma unroll
            for (int kc = 0; kc < 2; kc++) {
                uint32_t b0 = f2tf(sK[(8*nb + g) * 20 + 8*kc + t    ]);
                uint32_t b1 = f2tf(sK[(8*nb + g) * 20 + 8*kc + t + 4]);
                mma_tf32(sc[nb], qa[kc], b0, b1);
            }
        }

        // ---- P = exp(S), row sums, pack bf16 (C-layout == A-layout)
        uint32_t pa[16], pbv[16];
        #pragma unroll
        for (int nb = 0; nb < 16; nb++) {
            float e0 = __expf(sc[nb][0]);
            float e1 = __expf(sc[nb][1]);
            float e2 = __expf(sc[nb][2]);
            float e3 = __expf(sc[nb][3]);
            rs0 += e0 + e1;
            rs1 += e2 + e3;
            pa[nb]  = bf2(e1, e0);
            pbv[nb] = bf2(e3, e2);
        }

        // ---- O += P V^T (bf16), B frags via ldmatrix.x4 on sV [c][j]
        #pragma unroll
        for (int s = 0; s < 8; s++) {
            const uint32_t a0 = pa[2*s], a1 = pbv[2*s];
            const uint32_t a2 = pa[2*s+1], a3 = pbv[2*s+1];
            #pragma unroll
            for (int nbp = 0; nbp < 8; nbp++) {
                uint32_t r0, r1, r2, r3;
                ldm4(r0, r1, r2, r3, vbase + (uint32_t)(nbp * 4352 + s * 32) + vlane);
                mma_bf16(o[2*nbp],     a0, a1, a2, a3, r0, r1);
                mma_bf16(o[2*nbp + 1], a0, a1, a2, a3, r2, r3);
            }
        }
        __syncthreads();
    }

    // ---- normalize by row sums
    rs0 += __shfl_xor_sync(0xffffffffu, rs0, 1);
    rs0 += __shfl_xor_sync(0xffffffffu, rs0, 2);
    rs1 += __shfl_xor_sync(0xffffffffu, rs1, 1);
    rs1 += __shfl_xor_sync(0xffffffffu, rs1, 2);
    const float il0 = 1.f / rs0, il1 = 1.f / rs1;
    #pragma unroll
    for (int nb = 0; nb < 16; nb++) {
        o[nb][0] *= il0; o[nb][1] *= il0;
        o[nb][2] *= il1; o[nb][3] *= il1;
    }

    // ---- fused projection (tf32): proj[q][e] = sum_c O[q][c] pw[e][c]
    const float* pwS = (const float*)(sm + OFF_PW);
    const int src0 = (lane & ~3) | (t >> 1);
    const int src1 = src0 + 2;
    const bool odd = (t & 1);
    float pr[16][4];
    #pragma unroll
    for (int nb = 0; nb < 16; nb++)
        #pragma unroll
        for (int i = 0; i < 4; i++) pr[nb][i] = 0.f;

    #pragma unroll
    for (int kc = 0; kc < 16; kc++) {
        // relayout O C-frag -> tf32 A-frag via shuffles
        float x0 = __shfl_sync(0xffffffffu, o[kc][0], src0);
        float x1 = __shfl_sync(0xffffffffu, o[kc][1], src0);
        float y0 = __shfl_sync(0xffffffffu, o[kc][2], src0);
        float y1 = __shfl_sync(0xffffffffu, o[kc][3], src0);
        float x2 = __shfl_sync(0xffffffffu, o[kc][0], src1);
        float x3 = __shfl_sync(0xffffffffu, o[kc][1], src1);
        float y2 = __shfl_sync(0xffffffffu, o[kc][2], src1);
        float y3 = __shfl_sync(0xffffffffu, o[kc][3], src1);
        uint32_t a[4];
        a[0] = f2tf(odd ? x1 : x0);
        a[1] = f2tf(odd ? y1 : y0);
        a[2] = f2tf(odd ? x3 : x2);
        a[3] = f2tf(odd ? y3 : y2);
        #pragma unroll
        for (int nb = 0; nb < 16; nb++) {
            uint32_t b0 = f2tf(pwS[(8*nb + g) * 132 + 8*kc + t    ]);
            uint32_t b1 = f2tf(pwS[(8*nb + g) * 132 + 8*kc + t + 4]);
            mma_tf32(pr[nb], a, b0, b1);
        }
    }
    __syncthreads();   // all warps done reading p_w before stage overlay

    // ---- stage [e][q] (overlaying p_w), then bias + residual + STG
    float* stg = (float*)(sm + OFF_PW);
    #pragma unroll
    for (int nb = 0; nb < 16; nb++) {
        int e = 8*nb + 2*t;
        stg[(e    ) * 132 + 16*w + g    ] = pr[nb][0];
        stg[(e + 1) * 132 + 16*w + g    ] = pr[nb][1];
        stg[(e    ) * 132 + 16*w + g + 8] = pr[nb][2];
        stg[(e + 1) * 132 + 16*w + g + 8] = pr[nb][3];
    }
    __syncthreads();

    #pragma unroll
    for (int it = 0; it < 16; it++) {
        int idx = tid + it * 256;
        int e = idx >> 5, qq = idx & 31;
        float4 v4 = *(float4*)&stg[e * 132 + qq * 4];
        float bias = __ldg(pb + e);
        size_t gi = ((size_t)b * C + e) * NN + q0 + qq * 4;
        float4 xr = *(const float4*)&x[gi];
        v4.x += bias + xr.x; v4.y += bias + xr.y;
        v4.z += bias + xr.z; v4.w += bias + xr.w;
        *(float4*)&out[gi] = v4;
    }
}

// ---------------- launch -----------------------------------------------------
extern "C" void kernel_launch(void* const* d_in, const int* in_sizes, int n_in,
                              void* d_out, int out_size)
{
    const float* x    = (const float*)d_in[0];
    const float* gn_w = (const float*)d_in[1];
    const float* gn_b = (const float*)d_in[2];
    const float* q_w  = (const float*)d_in[3];
    const float* q_b  = (const float*)d_in[4];
    const float* k_w  = (const float*)d_in[5];
    const float* k_b  = (const float*)d_in[6];
    const float* v_w  = (const float*)d_in[7];
    const float* v_b  = (const float*)d_in[8];
    const float* p_w  = (const float*)d_in[9];
    const float* p_b  = (const float*)d_in[10];
    float* out = (float*)d_out;

    float *h, *qt, *kt;
    __nv_bfloat16* v;
    cudaGetSymbolAddress((void**)&h,  g_h);
    cudaGetSymbolAddress((void**)&qt, g_qt);
    cudaGetSymbolAddress((void**)&kt, g_kt);
    cudaGetSymbolAddress((void**)&v,  g_v);

    cudaFuncSetAttribute(flash_mma_kernel,
                         cudaFuncAttributeMaxDynamicSharedMemorySize, SMEM_FL);

    gn_kernel<<<BATCH * G, 256>>>(x, gn_w, gn_b, h);

    qk_proj_kernel<<<dim3(NN / 512, 1, BATCH), 256>>>(q_w, q_b, h, qt, 0.25f);
    qk_proj_kernel<<<dim3(NN / 512, 1, BATCH), 256>>>(k_w, k_b, h, kt, 1.0f);
    vproj_kernel<<<dim3(NN / 512, C / 8, BATCH), 256>>>(v_w, v_b, h, v);

    flash_mma_kernel<<<BATCH * 32, 256, SMEM_FL>>>(qt, kt, v, p_w, p_b, x, out);
}

// round 5
// speedup vs baseline: 7.6132x; 1.1502x over previous
#include <cuda_runtime.h>
#include <cuda_bf16.h>
#include <cstdint>
#include <math.h>

#define BATCH 8
#define C 128
#define NN 4096
#define D 16
#define G 32
#define CPG (C / G)
#define EPS 1e-5f

// ---------------- scratch ----------------------------------------------------
__device__ float          g_h  [BATCH * C * NN];   // group-normed [B,C,N]
__device__ float          g_qt [BATCH * NN * D];   // q [B,N,16] (pre-scaled)
__device__ float          g_kt [BATCH * NN * D];   // k [B,N,16]
__device__ __nv_bfloat16  g_v  [BATCH * C * NN];   // v [B,C,N] bf16
__device__ __nv_bfloat16  g_pwb[C * C];            // p_w bf16 [e][c]

// ---------------- GroupNorm --------------------------------------------------
__global__ __launch_bounds__(256) void gn_kernel(
    const float* __restrict__ x, const float* __restrict__ w,
    const float* __restrict__ bvec, float* __restrict__ h)
{
    const int b = blockIdx.x >> 5;
    const int g = blockIdx.x & 31;
    const int c0 = g * CPG;
    const float* xp = x + ((size_t)b * C + c0) * NN;
    float* hp = h + ((size_t)b * C + c0) * NN;

    const int TOT = CPG * NN;
    float s = 0.f, s2 = 0.f;
    for (int idx = threadIdx.x; idx < TOT; idx += 256) {
        float v = xp[idx];
        s += v; s2 += v * v;
    }
    __shared__ float red[16];
    int lane = threadIdx.x & 31, wid = threadIdx.x >> 5;
    #pragma unroll
    for (int o = 16; o > 0; o >>= 1) {
        s  += __shfl_xor_sync(0xffffffffu, s,  o);
        s2 += __shfl_xor_sync(0xffffffffu, s2, o);
    }
    if (lane == 0) { red[wid] = s; red[8 + wid] = s2; }
    __syncthreads();
    if (wid == 0) {
        float a = (lane < 8) ? red[lane] : 0.f;
        float a2 = (lane < 8) ? red[8 + lane] : 0.f;
        #pragma unroll
        for (int o = 4; o > 0; o >>= 1) {
            a  += __shfl_xor_sync(0xffffffffu, a,  o);
            a2 += __shfl_xor_sync(0xffffffffu, a2, o);
        }
        if (lane == 0) { red[0] = a; red[1] = a2; }
    }
    __syncthreads();
    const float inv_n = 1.f / (float)TOT;
    float mean = red[0] * inv_n;
    float var = red[1] * inv_n - mean * mean;
    float inv = rsqrtf(var + EPS);
    for (int idx = threadIdx.x; idx < TOT; idx += 256) {
        int c = idx >> 12;
        float v = (xp[idx] - mean) * inv;
        hp[idx] = v * w[c0 + c] + bvec[c0 + c];
    }
}

// ---------------- p_w -> bf16 ------------------------------------------------
__global__ void pwcvt_kernel(const float* __restrict__ pw,
                             __nv_bfloat16* __restrict__ pwb)
{
    int i = blockIdx.x * 1024 + threadIdx.x;
    pwb[i] = __float2bfloat16_rn(pw[i]);
}

// ---------------- mma helpers ------------------------------------------------
__device__ __forceinline__ uint32_t smem_u32(const void* p) {
    uint32_t a;
    asm("{ .reg .u64 t; cvta.to.shared.u64 t, %1; cvt.u32.u64 %0, t; }" : "=r"(a) : "l"(p));
    return a;
}
__device__ __forceinline__ void cpa16(uint32_t s, const void* g) {
    asm volatile("cp.async.cg.shared.global [%0], [%1], 16;" :: "r"(s), "l"(g));
}
#define CP_COMMIT() asm volatile("cp.async.commit_group;" ::: "memory")
#define CP_WAIT1()  asm volatile("cp.async.wait_group 1;" ::: "memory")
#define CP_WAIT0()  asm volatile("cp.async.wait_group 0;" ::: "memory")

__device__ __forceinline__ uint32_t f2tf(float f) {
    uint32_t u; asm("cvt.rna.tf32.f32 %0, %1;" : "=r"(u) : "f"(f)); return u;
}
__device__ __forceinline__ uint32_t bf2(float hi, float lo) {
    uint32_t r; asm("cvt.rn.bf16x2.f32 %0, %1, %2;" : "=r"(r) : "f"(hi), "f"(lo)); return r;
}
__device__ __forceinline__ void mma_tf32(float* c, const uint32_t* a,
                                         uint32_t b0, uint32_t b1) {
    asm volatile(
        "mma.sync.aligned.m16n8k8.row.col.f32.tf32.tf32.f32 "
        "{%0,%1,%2,%3},{%4,%5,%6,%7},{%8,%9},{%0,%1,%2,%3};"
        : "+f"(c[0]), "+f"(c[1]), "+f"(c[2]), "+f"(c[3])
        : "r"(a[0]), "r"(a[1]), "r"(a[2]), "r"(a[3]), "r"(b0), "r"(b1));
}
__device__ __forceinline__ void mma_bf16(float* c, uint32_t a0, uint32_t a1,
                                         uint32_t a2, uint32_t a3,
                                         uint32_t b0, uint32_t b1) {
    asm volatile(
        "mma.sync.aligned.m16n8k16.row.col.f32.bf16.bf16.f32 "
        "{%0,%1,%2,%3},{%4,%5,%6,%7},{%8,%9},{%0,%1,%2,%3};"
        : "+f"(c[0]), "+f"(c[1]), "+f"(c[2]), "+f"(c[3])
        : "r"(a0), "r"(a1), "r"(a2), "r"(a3), "r"(b0), "r"(b1));
}
__device__ __forceinline__ void ldm4(uint32_t& r0, uint32_t& r1, uint32_t& r2,
                                     uint32_t& r3, uint32_t addr) {
    asm volatile("ldmatrix.sync.aligned.m8n8.x4.shared.b16 {%0,%1,%2,%3}, [%4];"
                 : "=r"(r0), "=r"(r1), "=r"(r2), "=r"(r3) : "r"(addr));
}

// ============================================================================
//        fused QKV projection (tf32 mma): 160 outputs from h tile
// ============================================================================
// smem: hT [128n][132c] tf32  67584 | Ws [160e][132c] tf32 84480 (overlaid by
// vstage [128c][132n] bf16 33792 in epilogue) | bias 160 f32
#define PJ_HT   0
#define PJ_WS   67584
#define PJ_BIAS 152064
#define SMEM_PJ 152704

__global__ __launch_bounds__(256) void qkv_proj_kernel(
    const float* __restrict__ qw, const float* __restrict__ qb,
    const float* __restrict__ kw, const float* __restrict__ kb,
    const float* __restrict__ vw, const float* __restrict__ vb,
    const float* __restrict__ h,
    float* __restrict__ qt, float* __restrict__ kt,
    __nv_bfloat16* __restrict__ vout)
{
    extern __shared__ char sm[];
    uint32_t* hT = (uint32_t*)(sm + PJ_HT);
    uint32_t* Ws = (uint32_t*)(sm + PJ_WS);
    float* bs = (float*)(sm + PJ_BIAS);
    const int tid = threadIdx.x;
    const int w = tid >> 5, lane = tid & 31;
    const int g = lane >> 2, t = lane & 3;
    const int n0 = blockIdx.x * 128;
    const int b = blockIdx.y;

    // load weights (tf32) + biases
    for (int u = tid; u < 160 * 128; u += 256) {
        int e = u >> 7, c = u & 127;
        float wv;
        if (e < 16)      wv = qw[e * C + c];
        else if (e < 32) wv = kw[(e - 16) * C + c];
        else             wv = vw[(e - 32) * C + c];
        Ws[e * 132 + c] = f2tf(wv);
    }
    if (tid < 160) {
        float bv;
        if (tid < 16)      bv = qb[tid];
        else if (tid < 32) bv = kb[tid - 16];
        else               bv = vb[tid - 32];
        bs[tid] = bv;
    }
    // load h tile transposed -> hT[n][c] (tf32)
    for (int u = tid; u < 128 * 128; u += 256) {
        int n = u & 127, c = u >> 7;
        float hv = h[((size_t)b * C + c) * NN + n0 + n];
        hT[n * 132 + c] = f2tf(hv);
    }
    __syncthreads();

    // A fragments: rows 16w+g / +8
    uint32_t af[16][4];
    #pragma unroll
    for (int kc = 0; kc < 16; kc++) {
        af[kc][0] = hT[(16 * w + g    ) * 132 + 8 * kc + t    ];
        af[kc][1] = hT[(16 * w + g + 8) * 132 + 8 * kc + t    ];
        af[kc][2] = hT[(16 * w + g    ) * 132 + 8 * kc + t + 4];
        af[kc][3] = hT[(16 * w + g + 8) * 132 + 8 * kc + t + 4];
    }

    float pr[20][4];
    #pragma unroll
    for (int nb = 0; nb < 20; nb++)
        #pragma unroll
        for (int i = 0; i < 4; i++) pr[nb][i] = 0.f;

    #pragma unroll
    for (int kc = 0; kc < 16; kc++) {
        #pragma unroll
        for (int nb = 0; nb < 20; nb++) {
            uint32_t b0 = Ws[(8 * nb + g) * 132 + 8 * kc + t    ];
            uint32_t b1 = Ws[(8 * nb + g) * 132 + 8 * kc + t + 4];
            mma_tf32(pr[nb], af[kc], b0, b1);
        }
    }

    // q/k epilogue (direct gmem, f32)
    const int r0 = 16 * w + g, r1 = r0 + 8;
    #pragma unroll
    for (int nb = 0; nb < 4; nb++) {
        int e = 8 * nb + 2 * t;
        float b0 = bs[e], b1 = bs[e + 1];
        if (e < 16) {   // q: scale 0.25
            float2 lo = make_float2((pr[nb][0] + b0) * 0.25f, (pr[nb][1] + b1) * 0.25f);
            float2 hi = make_float2((pr[nb][2] + b0) * 0.25f, (pr[nb][3] + b1) * 0.25f);
            *(float2*)&qt[((size_t)b * NN + n0 + r0) * D + e] = lo;
            *(float2*)&qt[((size_t)b * NN + n0 + r1) * D + e] = hi;
        } else {        // k
            float2 lo = make_float2(pr[nb][0] + b0, pr[nb][1] + b1);
            float2 hi = make_float2(pr[nb][2] + b0, pr[nb][3] + b1);
            *(float2*)&kt[((size_t)b * NN + n0 + r0) * D + e - 16] = lo;
            *(float2*)&kt[((size_t)b * NN + n0 + r1) * D + e - 16] = hi;
        }
    }
    __syncthreads();   // all warps done reading Ws before vstage overlay

    // v epilogue: stage [c][n] bf16 over Ws, then coalesced STG
    __nv_bfloat16* vstage = (__nv_bfloat16*)(sm + PJ_WS);
    #pragma unroll
    for (int nb = 4; nb < 20; nb++) {
        int e = 8 * nb + 2 * t;
        int cv = e - 32;
        float b0 = bs[e], b1 = bs[e + 1];
        vstage[(cv    ) * 132 + r0] = __float2bfloat16_rn(pr[nb][0] + b0);
        vstage[(cv + 1) * 132 + r0] = __float2bfloat16_rn(pr[nb][1] + b1);
        vstage[(cv    ) * 132 + r1] = __float2bfloat16_rn(pr[nb][2] + b0);
        vstage[(cv + 1) * 132 + r1] = __float2bfloat16_rn(pr[nb][3] + b1);
    }
    __syncthreads();
    for (int u = tid; u < 128 * 32; u += 256) {
        int c = u >> 5, nc = u & 31;
        *(uint64_t*)&vout[((size_t)b * C + c) * NN + n0 + nc * 4] =
            *(const uint64_t*)&vstage[c * 132 + nc * 4];
    }
}

// ============================================================================
//        flash attention: mma.sync (tf32 S, bf16 PV) + fused bf16 proj
// ============================================================================
#define OFF_Q   0        // f32 [128][20]   10240
#define OFF_K0  10240
#define OFF_K1  20480
#define OFF_V0  30720    // bf16 [128][136] 34816
#define OFF_V1  65536
#define OFF_PW  0        // bf16 [128][136] 34816 (overlays Q/K after mainloop)
#define OFF_STG 34816    // f32 [128][132]  67584 (overlays V)
#define SMEM_FL 102400

__device__ __forceinline__ void issue_tile(uint32_t sb, int buf,
    const float* __restrict__ kt, const __nv_bfloat16* __restrict__ vb,
    int b, int j0, int tid)
{
    uint32_t kdst = sb + (buf ? OFF_K1 : OFF_K0);
    #pragma unroll
    for (int u = tid; u < 512; u += 256) {
        int row = u >> 2, cc = u & 3;
        cpa16(kdst + row * 80 + cc * 16,
              kt + ((size_t)(b * NN + j0 + row)) * D + cc * 4);
    }
    uint32_t vdst = sb + (buf ? OFF_V1 : OFF_V0);
    #pragma unroll
    for (int u = tid; u < 2048; u += 256) {
        int c = u >> 4, cc = u & 15;
        cpa16(vdst + c * 272 + cc * 16,
              vb + ((size_t)(b * C + c)) * NN + j0 + cc * 8);
    }
}

__global__ __launch_bounds__(256, 2) void flash_mma_kernel(
    const float* __restrict__ qt, const float* __restrict__ kt,
    const __nv_bfloat16* __restrict__ vb, const __nv_bfloat16* __restrict__ pwb,
    const float* __restrict__ pb, const float* __restrict__ x,
    float* __restrict__ out)
{
    extern __shared__ char sm[];
    const uint32_t sb = smem_u32(sm);
    const int tid = threadIdx.x;
    const int w = tid >> 5;
    const int lane = tid & 31;
    const int g = lane >> 2, t = lane & 3;
    const int b = blockIdx.x >> 5;
    const int q0 = (blockIdx.x & 31) * 128;

    const int rowsel = (lane & 7) + ((lane >> 4) << 3);
    const int ksel = (lane >> 3) & 1;
    const uint32_t vlane = (uint32_t)(rowsel * 272 + ksel * 16);

    // prologue: Q + tile 0
    #pragma unroll
    for (int u = tid; u < 512; u += 256) {
        int row = u >> 2, cc = u & 3;
        cpa16(sb + OFF_Q + row * 80 + cc * 16,
              qt + ((size_t)(b * NN + q0 + row)) * D + cc * 4);
    }
    issue_tile(sb, 0, kt, vb, b, 0, tid);
    CP_COMMIT();

    const float* sQ = (const float*)(sm + OFF_Q);
    uint32_t qa[2][4];
    float o[16][4];
    #pragma unroll
    for (int nb = 0; nb < 16; nb++)
        #pragma unroll
        for (int i = 0; i < 4; i++) o[nb][i] = 0.f;
    float rs0 = 0.f, rs1 = 0.f;

    for (int tt = 0; tt < 32; tt++) {
        const int buf = tt & 1;
        if (tt < 31) {
            issue_tile(sb, buf ^ 1, kt, vb, b, (tt + 1) * 128, tid);
            CP_COMMIT();
            CP_WAIT1();
        } else {
            CP_WAIT0();
        }
        __syncthreads();

        if (tt == 0) {
            #pragma unroll
            for (int kc = 0; kc < 2; kc++) {
                qa[kc][0] = f2tf(sQ[(16*w + g    ) * 20 + 8*kc + t    ]);
                qa[kc][1] = f2tf(sQ[(16*w + g + 8) * 20 + 8*kc + t    ]);
                qa[kc][2] = f2tf(sQ[(16*w + g    ) * 20 + 8*kc + t + 4]);
                qa[kc][3] = f2tf(sQ[(16*w + g + 8) * 20 + 8*kc + t + 4]);
            }
        }

        const float* sK = (const float*)(sm + (buf ? OFF_K1 : OFF_K0));
        const uint32_t vbase = sb + (buf ? OFF_V1 : OFF_V0);

        // ---- S = Q K^T (tf32) fused with exp -> P bf16 packs
        uint32_t pa[16], pbv[16];
        #pragma unroll
        for (int nb = 0; nb < 16; nb++) {
            float sc[4] = {0.f, 0.f, 0.f, 0.f};
            #pragma unroll
            for (int kc = 0; kc < 2; kc++) {
                uint32_t b0 = f2tf(sK[(8*nb + g) * 20 + 8*kc + t    ]);
                uint32_t b1 = f2tf(sK[(8*nb + g) * 20 + 8*kc + t + 4]);
                mma_tf32(sc, qa[kc], b0, b1);
            }
            float e0 = __expf(sc[0]);
            float e1 = __expf(sc[1]);
            float e2 = __expf(sc[2]);
            float e3 = __expf(sc[3]);
            rs0 += e0 + e1;
            rs1 += e2 + e3;
            pa[nb]  = bf2(e1, e0);
            pbv[nb] = bf2(e3, e2);
        }

        if (tt == 31) {
            // K/Q dead after last S-mma: load p_w (bf16) over them
            __syncthreads();
            #pragma unroll
            for (int u = tid; u < 2048; u += 256) {
                int row = u >> 4, cc = u & 15;
                cpa16(sb + OFF_PW + row * 272 + cc * 16, pwb + row * C + cc * 8);
            }
            CP_COMMIT();
        }

        // ---- O += P V^T (bf16)
        #pragma unroll
        for (int s = 0; s < 8; s++) {
            const uint32_t a0 = pa[2*s], a1 = pbv[2*s];
            const uint32_t a2 = pa[2*s+1], a3 = pbv[2*s+1];
            #pragma unroll
            for (int nbp = 0; nbp < 8; nbp++) {
                uint32_t r0, r1, r2, r3;
                ldm4(r0, r1, r2, r3, vbase + (uint32_t)(nbp * 4352 + s * 32) + vlane);
                mma_bf16(o[2*nbp],     a0, a1, a2, a3, r0, r1);
                mma_bf16(o[2*nbp + 1], a0, a1, a2, a3, r2, r3);
            }
        }
        __syncthreads();
    }

    // ---- normalize by row sums
    rs0 += __shfl_xor_sync(0xffffffffu, rs0, 1);
    rs0 += __shfl_xor_sync(0xffffffffu, rs0, 2);
    rs1 += __shfl_xor_sync(0xffffffffu, rs1, 1);
    rs1 += __shfl_xor_sync(0xffffffffu, rs1, 2);
    const float il0 = 1.f / rs0, il1 = 1.f / rs1;

    // ---- O -> bf16 A-fragments
    uint32_t oa0[16], oa1[16];
    #pragma unroll
    for (int nb = 0; nb < 16; nb++) {
        oa0[nb] = bf2(o[nb][1] * il0, o[nb][0] * il0);
        oa1[nb] = bf2(o[nb][3] * il1, o[nb][2] * il1);
    }

    CP_WAIT0();          // p_w tile in smem
    __syncthreads();

    // ---- fused projection (bf16): proj[q][e] = sum_c O[q][c] pw[e][c]
    float pr[16][4];
    #pragma unroll
    for (int nb = 0; nb < 16; nb++)
        #pragma unroll
        for (int i = 0; i < 4; i++) pr[nb][i] = 0.f;
    const uint32_t pwbase = sb + OFF_PW;
    #pragma unroll
    for (int s = 0; s < 8; s++) {
        const uint32_t a0 = oa0[2*s], a1 = oa1[2*s];
        const uint32_t a2 = oa0[2*s+1], a3 = oa1[2*s+1];
        #pragma unroll
        for (int nbp = 0; nbp < 8; nbp++) {
            uint32_t r0, r1, r2, r3;
            ldm4(r0, r1, r2, r3, pwbase + (uint32_t)(nbp * 4352 + s * 32) + vlane);
            mma_bf16(pr[2*nbp],     a0, a1, a2, a3, r0, r1);
            mma_bf16(pr[2*nbp + 1], a0, a1, a2, a3, r2, r3);
        }
    }

    // ---- stage [e][q] (over V region), then bias + residual + STG
    float* stg = (float*)(sm + OFF_STG);
    #pragma unroll
    for (int nb = 0; nb < 16; nb++) {
        int e = 8*nb + 2*t;
        stg[(e    ) * 132 + 16*w + g    ] = pr[nb][0];
        stg[(e + 1) * 132 + 16*w + g    ] = pr[nb][1];
        stg[(e    ) * 132 + 16*w + g + 8] = pr[nb][2];
        stg[(e + 1) * 132 + 16*w + g + 8] = pr[nb][3];
    }
    __syncthreads();

    #pragma unroll
    for (int it = 0; it < 16; it++) {
        int idx = tid + it * 256;
        int e = idx >> 5, qq = idx & 31;
        float4 v4 = *(float4*)&stg[e * 132 + qq * 4];
        float bias = __ldg(pb + e);
        size_t gi = ((size_t)b * C + e) * NN + q0 + qq * 4;
        float4 xr = *(const float4*)&x[gi];
        v4.x += bias + xr.x; v4.y += bias + xr.y;
        v4.z += bias + xr.z; v4.w += bias + xr.w;
        *(float4*)&out[gi] = v4;
    }
}

// ---------------- launch -----------------------------------------------------
extern "C" void kernel_launch(void* const* d_in, const int* in_sizes, int n_in,
                              void* d_out, int out_size)
{
    const float* x    = (const float*)d_in[0];
    const float* gn_w = (const float*)d_in[1];
    const float* gn_b = (const float*)d_in[2];
    const float* q_w  = (const float*)d_in[3];
    const float* q_b  = (const float*)d_in[4];
    const float* k_w  = (const float*)d_in[5];
    const float* k_b  = (const float*)d_in[6];
    const float* v_w  = (const float*)d_in[7];
    const float* v_b  = (const float*)d_in[8];
    const float* p_w  = (const float*)d_in[9];
    const float* p_b  = (const float*)d_in[10];
    float* out = (float*)d_out;

    float *h, *qt, *kt;
    __nv_bfloat16 *v, *pwb;
    cudaGetSymbolAddress((void**)&h,   g_h);
    cudaGetSymbolAddress((void**)&qt,  g_qt);
    cudaGetSymbolAddress((void**)&kt,  g_kt);
    cudaGetSymbolAddress((void**)&v,   g_v);
    cudaGetSymbolAddress((void**)&pwb, g_pwb);

    cudaFuncSetAttribute(flash_mma_kernel,
                         cudaFuncAttributeMaxDynamicSharedMemorySize, SMEM_FL);
    cudaFuncSetAttribute(qkv_proj_kernel,
                         cudaFuncAttributeMaxDynamicSharedMemorySize, SMEM_PJ);

    gn_kernel<<<BATCH * G, 256>>>(x, gn_w, gn_b, h);
    pwcvt_kernel<<<16, 1024>>>(p_w, pwb);

    qkv_proj_kernel<<<dim3(NN / 128, BATCH), 256, SMEM_PJ>>>(
        q_w, q_b, k_w, k_b, v_w, v_b, h, qt, kt, v);

    flash_mma_kernel<<<BATCH * 32, 256, SMEM_FL>>>(qt, kt, v, pwb, p_b, x, out);
}

// round 6
// speedup vs baseline: 8.4295x; 1.1072x over previous
#include <cuda_runtime.h>
#include <cuda_bf16.h>
#include <cstdint>
#include <math.h>

#define BATCH 8
#define C 128
#define NN 4096
#define D 16
#define G 32
#define CPG (C / G)
#define EPS 1e-5f
#define SCALE_Q 0.36067376022224085f   // 0.25 * log2(e)

// ---------------- scratch ----------------------------------------------------
__device__ float          g_qt [BATCH * NN * D];   // q [B,N,16] tf32 bits, scaled
__device__ float          g_kt [BATCH * NN * D];   // k [B,N,16] tf32 bits
__device__ __nv_bfloat16  g_v  [BATCH * C * NN];   // v [B,C,N] bf16
__device__ __nv_bfloat16  g_pwb[C * C];            // p_w bf16 [e][c]
__device__ float          g_st [BATCH * G * 2];    // groupnorm (mean, rstd)

// ---------------- GroupNorm stats only ---------------------------------------
__global__ __launch_bounds__(256) void gn_stats_kernel(
    const float* __restrict__ x, float* __restrict__ st)
{
    const int b = blockIdx.x >> 5;
    const int g = blockIdx.x & 31;
    const float* xp = x + ((size_t)b * C + g * CPG) * NN;

    const int TOT = CPG * NN;
    float s = 0.f, s2 = 0.f;
    for (int idx = threadIdx.x; idx < TOT; idx += 256) {
        float v = xp[idx];
        s += v; s2 += v * v;
    }
    __shared__ float red[16];
    int lane = threadIdx.x & 31, wid = threadIdx.x >> 5;
    #pragma unroll
    for (int o = 16; o > 0; o >>= 1) {
        s  += __shfl_xor_sync(0xffffffffu, s,  o);
        s2 += __shfl_xor_sync(0xffffffffu, s2, o);
    }
    if (lane == 0) { red[wid] = s; red[8 + wid] = s2; }
    __syncthreads();
    if (wid == 0) {
        float a = (lane < 8) ? red[lane] : 0.f;
        float a2 = (lane < 8) ? red[8 + lane] : 0.f;
        #pragma unroll
        for (int o = 4; o > 0; o >>= 1) {
            a  += __shfl_xor_sync(0xffffffffu, a,  o);
            a2 += __shfl_xor_sync(0xffffffffu, a2, o);
        }
        if (lane == 0) {
            const float inv_n = 1.f / (float)TOT;
            float mean = a * inv_n;
            float var = a2 * inv_n - mean * mean;
            st[blockIdx.x * 2]     = mean;
            st[blockIdx.x * 2 + 1] = rsqrtf(var + EPS);
        }
    }
}

// ---------------- p_w -> bf16 ------------------------------------------------
__global__ void pwcvt_kernel(const float* __restrict__ pw,
                             __nv_bfloat16* __restrict__ pwb)
{
    int i = blockIdx.x * 1024 + threadIdx.x;
    pwb[i] = __float2bfloat16_rn(pw[i]);
}

// ---------------- mma helpers ------------------------------------------------
__device__ __forceinline__ uint32_t smem_u32(const void* p) {
    uint32_t a;
    asm("{ .reg .u64 t; cvta.to.shared.u64 t, %1; cvt.u32.u64 %0, t; }" : "=r"(a) : "l"(p));
    return a;
}
__device__ __forceinline__ void cpa16(uint32_t s, const void* g) {
    asm volatile("cp.async.cg.shared.global [%0], [%1], 16;" :: "r"(s), "l"(g));
}
#define CP_COMMIT() asm volatile("cp.async.commit_group;" ::: "memory")
#define CP_WAIT1()  asm volatile("cp.async.wait_group 1;" ::: "memory")
#define CP_WAIT0()  asm volatile("cp.async.wait_group 0;" ::: "memory")

__device__ __forceinline__ uint32_t f2tf(float f) {
    uint32_t u; asm("cvt.rna.tf32.f32 %0, %1;" : "=r"(u) : "f"(f)); return u;
}
__device__ __forceinline__ float ex2f(float f) {
    float r; asm("ex2.approx.f32 %0, %1;" : "=f"(r) : "f"(f)); return r;
}
__device__ __forceinline__ uint32_t bf2(float hi, float lo) {
    uint32_t r; asm("cvt.rn.bf16x2.f32 %0, %1, %2;" : "=r"(r) : "f"(hi), "f"(lo)); return r;
}
__device__ __forceinline__ void mma_tf32(float* c, const uint32_t* a,
                                         uint32_t b0, uint32_t b1) {
    asm volatile(
        "mma.sync.aligned.m16n8k8.row.col.f32.tf32.tf32.f32 "
        "{%0,%1,%2,%3},{%4,%5,%6,%7},{%8,%9},{%0,%1,%2,%3};"
        : "+f"(c[0]), "+f"(c[1]), "+f"(c[2]), "+f"(c[3])
        : "r"(a[0]), "r"(a[1]), "r"(a[2]), "r"(a[3]), "r"(b0), "r"(b1));
}
__device__ __forceinline__ void mma_bf16(float* c, uint32_t a0, uint32_t a1,
                                         uint32_t a2, uint32_t a3,
                                         uint32_t b0, uint32_t b1) {
    asm volatile(
        "mma.sync.aligned.m16n8k16.row.col.f32.bf16.bf16.f32 "
        "{%0,%1,%2,%3},{%4,%5,%6,%7},{%8,%9},{%0,%1,%2,%3};"
        : "+f"(c[0]), "+f"(c[1]), "+f"(c[2]), "+f"(c[3])
        : "r"(a0), "r"(a1), "r"(a2), "r"(a3), "r"(b0), "r"(b1));
}
__device__ __forceinline__ void ldm4(uint32_t& r0, uint32_t& r1, uint32_t& r2,
                                     uint32_t& r3, uint32_t addr) {
    asm volatile("ldmatrix.sync.aligned.m8n8.x4.shared.b16 {%0,%1,%2,%3}, [%4];"
                 : "=r"(r0), "=r"(r1), "=r"(r2), "=r"(r3) : "r"(addr));
}

// ============================================================================
//   fused GN + QKV projection (tf32 mma): q/k written as tf32 bits, v bf16
// ============================================================================
#define PJ_HT   0              // [128n][132c] u32           67584
#define PJ_WS   67584          // [160e][132c] u32           84480 (vstage overlay)
#define PJ_BIAS 152064         // 160 f32                    640
#define PJ_SC   152704         // scale 128 + shift 128 f32  1024
#define SMEM_PJ 153728

__global__ __launch_bounds__(256) void qkv_proj_kernel(
    const float* __restrict__ qw, const float* __restrict__ qb,
    const float* __restrict__ kw, const float* __restrict__ kb,
    const float* __restrict__ vw, const float* __restrict__ vb,
    const float* __restrict__ gnw, const float* __restrict__ gnb,
    const float* __restrict__ st, const float* __restrict__ x,
    float* __restrict__ qt, float* __restrict__ kt,
    __nv_bfloat16* __restrict__ vout)
{
    extern __shared__ char sm[];
    uint32_t* hT = (uint32_t*)(sm + PJ_HT);
    uint32_t* Ws = (uint32_t*)(sm + PJ_WS);
    float* bs = (float*)(sm + PJ_BIAS);
    float* sc = (float*)(sm + PJ_SC);
    float* sh = sc + 128;
    const int tid = threadIdx.x;
    const int w = tid >> 5, lane = tid & 31;
    const int g = lane >> 2, t = lane & 3;
    const int n0 = blockIdx.x * 128;
    const int b = blockIdx.y;

    // per-channel normalization coefficients
    if (tid < 128) {
        float mean = st[(b * G + (tid >> 2)) * 2];
        float inv  = st[(b * G + (tid >> 2)) * 2 + 1];
        float s = gnw[tid] * inv;
        sc[tid] = s;
        sh[tid] = gnb[tid] - mean * s;
    }
    // weights (tf32) + biases
    for (int u = tid; u < 160 * 128; u += 256) {
        int e = u >> 7, c = u & 127;
        float wv;
        if (e < 16)      wv = qw[e * C + c];
        else if (e < 32) wv = kw[(e - 16) * C + c];
        else             wv = vw[(e - 32) * C + c];
        Ws[e * 132 + c] = f2tf(wv);
    }
    if (tid < 160) {
        float bv;
        if (tid < 16)      bv = qb[tid];
        else if (tid < 32) bv = kb[tid - 16];
        else               bv = vb[tid - 32];
        bs[tid] = bv;
    }
    __syncthreads();   // sc/sh ready before hT load uses them

    // h tile transposed, normalized on the fly -> hT[n][c] (tf32)
    for (int u = tid; u < 128 * 128; u += 256) {
        int n = u & 127, c = u >> 7;
        float hv = fmaf(x[((size_t)b * C + c) * NN + n0 + n], sc[c], sh[c]);
        hT[n * 132 + c] = f2tf(hv);
    }
    __syncthreads();

    uint32_t af[16][4];
    #pragma unroll
    for (int kc = 0; kc < 16; kc++) {
        af[kc][0] = hT[(16 * w + g    ) * 132 + 8 * kc + t    ];
        af[kc][1] = hT[(16 * w + g + 8) * 132 + 8 * kc + t    ];
        af[kc][2] = hT[(16 * w + g    ) * 132 + 8 * kc + t + 4];
        af[kc][3] = hT[(16 * w + g + 8) * 132 + 8 * kc + t + 4];
    }

    float pr[20][4];
    #pragma unroll
    for (int nb = 0; nb < 20; nb++)
        #pragma unroll
        for (int i = 0; i < 4; i++) pr[nb][i] = 0.f;

    #pragma unroll
    for (int kc = 0; kc < 16; kc++) {
        #pragma unroll
        for (int nb = 0; nb < 20; nb++) {
            uint32_t b0 = Ws[(8 * nb + g) * 132 + 8 * kc + t    ];
            uint32_t b1 = Ws[(8 * nb + g) * 132 + 8 * kc + t + 4];
            mma_tf32(pr[nb], af[kc], b0, b1);
        }
    }

    // q/k epilogue: pre-scaled (q), tf32-rounded bit patterns
    const int r0 = 16 * w + g, r1 = r0 + 8;
    #pragma unroll
    for (int nb = 0; nb < 4; nb++) {
        int e = 8 * nb + 2 * t;
        float b0 = bs[e], b1 = bs[e + 1];
        if (e < 16) {
            float2 lo = make_float2(
                __uint_as_float(f2tf((pr[nb][0] + b0) * SCALE_Q)),
                __uint_as_float(f2tf((pr[nb][1] + b1) * SCALE_Q)));
            float2 hi = make_float2(
                __uint_as_float(f2tf((pr[nb][2] + b0) * SCALE_Q)),
                __uint_as_float(f2tf((pr[nb][3] + b1) * SCALE_Q)));
            *(float2*)&qt[((size_t)b * NN + n0 + r0) * D + e] = lo;
            *(float2*)&qt[((size_t)b * NN + n0 + r1) * D + e] = hi;
        } else {
            float2 lo = make_float2(
                __uint_as_float(f2tf(pr[nb][0] + b0)),
                __uint_as_float(f2tf(pr[nb][1] + b1)));
            float2 hi = make_float2(
                __uint_as_float(f2tf(pr[nb][2] + b0)),
                __uint_as_float(f2tf(pr[nb][3] + b1)));
            *(float2*)&kt[((size_t)b * NN + n0 + r0) * D + e - 16] = lo;
            *(float2*)&kt[((size_t)b * NN + n0 + r1) * D + e - 16] = hi;
        }
    }
    __syncthreads();

    // v epilogue via bf16 stage (overlays Ws)
    __nv_bfloat16* vstage = (__nv_bfloat16*)(sm + PJ_WS);
    #pragma unroll
    for (int nb = 4; nb < 20; nb++) {
        int e = 8 * nb + 2 * t;
        int cv = e - 32;
        float b0 = bs[e], b1 = bs[e + 1];
        vstage[(cv    ) * 132 + r0] = __float2bfloat16_rn(pr[nb][0] + b0);
        vstage[(cv + 1) * 132 + r0] = __float2bfloat16_rn(pr[nb][1] + b1);
        vstage[(cv    ) * 132 + r1] = __float2bfloat16_rn(pr[nb][2] + b0);
        vstage[(cv + 1) * 132 + r1] = __float2bfloat16_rn(pr[nb][3] + b1);
    }
    __syncthreads();
    for (int u = tid; u < 128 * 32; u += 256) {
        int c = u >> 5, nc = u & 31;
        *(uint64_t*)&vout[((size_t)b * C + c) * NN + n0 + nc * 4] =
            *(const uint64_t*)&vstage[c * 132 + nc * 4];
    }
}

// ============================================================================
//        flash attention: mma.sync (tf32 S, bf16 PV) + fused bf16 proj
// ============================================================================
#define OFF_Q   0
#define OFF_K0  10240
#define OFF_K1  20480
#define OFF_V0  30720
#define OFF_V1  65536
#define OFF_PW  0
#define OFF_STG 34816
#define SMEM_FL 102400

__device__ __forceinline__ void issue_tile(uint32_t sb, int buf,
    const float* __restrict__ kt, const __nv_bfloat16* __restrict__ vb,
    int b, int j0, int tid)
{
    uint32_t kdst = sb + (buf ? OFF_K1 : OFF_K0);
    #pragma unroll
    for (int u = tid; u < 512; u += 256) {
        int row = u >> 2, cc = u & 3;
        cpa16(kdst + row * 80 + cc * 16,
              kt + ((size_t)(b * NN + j0 + row)) * D + cc * 4);
    }
    uint32_t vdst = sb + (buf ? OFF_V1 : OFF_V0);
    #pragma unroll
    for (int u = tid; u < 2048; u += 256) {
        int c = u >> 4, cc = u & 15;
        cpa16(vdst + c * 272 + cc * 16,
              vb + ((size_t)(b * C + c)) * NN + j0 + cc * 8);
    }
}

__global__ __launch_bounds__(256, 2) void flash_mma_kernel(
    const float* __restrict__ qt, const float* __restrict__ kt,
    const __nv_bfloat16* __restrict__ vb, const __nv_bfloat16* __restrict__ pwb,
    const float* __restrict__ pb, const float* __restrict__ x,
    float* __restrict__ out)
{
    extern __shared__ char sm[];
    const uint32_t sb = smem_u32(sm);
    const int tid = threadIdx.x;
    const int w = tid >> 5;
    const int lane = tid & 31;
    const int g = lane >> 2, t = lane & 3;
    const int b = blockIdx.x >> 5;
    const int q0 = (blockIdx.x & 31) * 128;

    const int rowsel = (lane & 7) + ((lane >> 4) << 3);
    const int ksel = (lane >> 3) & 1;
    const uint32_t vlane = (uint32_t)(rowsel * 272 + ksel * 16);

    #pragma unroll
    for (int u = tid; u < 512; u += 256) {
        int row = u >> 2, cc = u & 3;
        cpa16(sb + OFF_Q + row * 80 + cc * 16,
              qt + ((size_t)(b * NN + q0 + row)) * D + cc * 4);
    }
    issue_tile(sb, 0, kt, vb, b, 0, tid);
    CP_COMMIT();

    const uint32_t* sQ = (const uint32_t*)(sm + OFF_Q);
    uint32_t qa[2][4];
    float o[16][4];
    #pragma unroll
    for (int nb = 0; nb < 16; nb++)
        #pragma unroll
        for (int i = 0; i < 4; i++) o[nb][i] = 0.f;
    float rs0 = 0.f, rs1 = 0.f;

    for (int tt = 0; tt < 32; tt++) {
        const int buf = tt & 1;
        if (tt < 31) {
            issue_tile(sb, buf ^ 1, kt, vb, b, (tt + 1) * 128, tid);
            CP_COMMIT();
            CP_WAIT1();
        } else {
            CP_WAIT0();
        }
        __syncthreads();

        if (tt == 0) {   // pre-converted tf32 bits: plain loads
            #pragma unroll
            for (int kc = 0; kc < 2; kc++) {
                qa[kc][0] = sQ[(16*w + g    ) * 20 + 8*kc + t    ];
                qa[kc][1] = sQ[(16*w + g + 8) * 20 + 8*kc + t    ];
                qa[kc][2] = sQ[(16*w + g    ) * 20 + 8*kc + t + 4];
                qa[kc][3] = sQ[(16*w + g + 8) * 20 + 8*kc + t + 4];
            }
        }

        const uint32_t* sK = (const uint32_t*)(sm + (buf ? OFF_K1 : OFF_K0));
        const uint32_t vbase = sb + (buf ? OFF_V1 : OFF_V0);

        // ---- S = Q K^T (tf32, pre-scaled by log2e) fused with exp2
        uint32_t pa[16], pbv[16];
        #pragma unroll
        for (int nb = 0; nb < 16; nb++) {
            float scv[4] = {0.f, 0.f, 0.f, 0.f};
            #pragma unroll
            for (int kc = 0; kc < 2; kc++) {
                uint32_t b0 = sK[(8*nb + g) * 20 + 8*kc + t    ];
                uint32_t b1 = sK[(8*nb + g) * 20 + 8*kc + t + 4];
                mma_tf32(scv, qa[kc], b0, b1);
            }
            float e0 = ex2f(scv[0]);
            float e1 = ex2f(scv[1]);
            float e2 = ex2f(scv[2]);
            float e3 = ex2f(scv[3]);
            rs0 += e0 + e1;
            rs1 += e2 + e3;
            pa[nb]  = bf2(e1, e0);
            pbv[nb] = bf2(e3, e2);
        }

        if (tt == 31) {
            __syncthreads();
            #pragma unroll
            for (int u = tid; u < 2048; u += 256) {
                int row = u >> 4, cc = u & 15;
                cpa16(sb + OFF_PW + row * 272 + cc * 16, pwb + row * C + cc * 8);
            }
            CP_COMMIT();
        }

        // ---- O += P V^T (bf16)
        #pragma unroll
        for (int s = 0; s < 8; s++) {
            const uint32_t a0 = pa[2*s], a1 = pbv[2*s];
            const uint32_t a2 = pa[2*s+1], a3 = pbv[2*s+1];
            #pragma unroll
            for (int nbp = 0; nbp < 8; nbp++) {
                uint32_t r0, r1, r2, r3;
                ldm4(r0, r1, r2, r3, vbase + (uint32_t)(nbp * 4352 + s * 32) + vlane);
                mma_bf16(o[2*nbp],     a0, a1, a2, a3, r0, r1);
                mma_bf16(o[2*nbp + 1], a0, a1, a2, a3, r2, r3);
            }
        }
        __syncthreads();
    }

    rs0 += __shfl_xor_sync(0xffffffffu, rs0, 1);
    rs0 += __shfl_xor_sync(0xffffffffu, rs0, 2);
    rs1 += __shfl_xor_sync(0xffffffffu, rs1, 1);
    rs1 += __shfl_xor_sync(0xffffffffu, rs1, 2);
    const float il0 = 1.f / rs0, il1 = 1.f / rs1;

    uint32_t oa0[16], oa1[16];
    #pragma unroll
    for (int nb = 0; nb < 16; nb++) {
        oa0[nb] = bf2(o[nb][1] * il0, o[nb][0] * il0);
        oa1[nb] = bf2(o[nb][3] * il1, o[nb][2] * il1);
    }

    CP_WAIT0();
    __syncthreads();

    float pr[16][4];
    #pragma unroll
    for (int nb = 0; nb < 16; nb++)
        #pragma unroll
        for (int i = 0; i < 4; i++) pr[nb][i] = 0.f;
    const uint32_t pwbase = sb + OFF_PW;
    #pragma unroll
    for (int s = 0; s < 8; s++) {
        const uint32_t a0 = oa0[2*s], a1 = oa1[2*s];
        const uint32_t a2 = oa0[2*s+1], a3 = oa1[2*s+1];
        #pragma unroll
        for (int nbp = 0; nbp < 8; nbp++) {
            uint32_t r0, r1, r2, r3;
            ldm4(r0, r1, r2, r3, pwbase + (uint32_t)(nbp * 4352 + s * 32) + vlane);
            mma_bf16(pr[2*nbp],     a0, a1, a2, a3, r0, r1);
            mma_bf16(pr[2*nbp + 1], a0, a1, a2, a3, r2, r3);
        }
    }

    float* stg = (float*)(sm + OFF_STG);
    #pragma unroll
    for (int nb = 0; nb < 16; nb++) {
        int e = 8*nb + 2*t;
        stg[(e    ) * 132 + 16*w + g    ] = pr[nb][0];
        stg[(e + 1) * 132 + 16*w + g    ] = pr[nb][1];
        stg[(e    ) * 132 + 16*w + g + 8] = pr[nb][2];
        stg[(e + 1) * 132 + 16*w + g + 8] = pr[nb][3];
    }
    __syncthreads();

    #pragma unroll
    for (int it = 0; it < 16; it++) {
        int idx = tid + it * 256;
        int e = idx >> 5, qq = idx & 31;
        float4 v4 = *(float4*)&stg[e * 132 + qq * 4];
        float bias = __ldg(pb + e);
        size_t gi = ((size_t)b * C + e) * NN + q0 + qq * 4;
        float4 xr = *(const float4*)&x[gi];
        v4.x += bias + xr.x; v4.y += bias + xr.y;
        v4.z += bias + xr.z; v4.w += bias + xr.w;
        *(float4*)&out[gi] = v4;
    }
}

// ---------------- launch -----------------------------------------------------
extern "C" void kernel_launch(void* const* d_in, const int* in_sizes, int n_in,
                              void* d_out, int out_size)
{
    const float* x    = (const float*)d_in[0];
    const float* gn_w = (const float*)d_in[1];
    const float* gn_b = (const float*)d_in[2];
    const float* q_w  = (const float*)d_in[3];
    const float* q_b  = (const float*)d_in[4];
    const float* k_w  = (const float*)d_in[5];
    const float* k_b  = (const float*)d_in[6];
    const float* v_w  = (const float*)d_in[7];
    const float* v_b  = (const float*)d_in[8];
    const float* p_w  = (const float*)d_in[9];
    const float* p_b  = (const float*)d_in[10];
    float* out = (float*)d_out;

    float *qt, *kt, *st;
    __nv_bfloat16 *v, *pwb;
    cudaGetSymbolAddress((void**)&qt,  g_qt);
    cudaGetSymbolAddress((void**)&kt,  g_kt);
    cudaGetSymbolAddress((void**)&v,   g_v);
    cudaGetSymbolAddress((void**)&pwb, g_pwb);
    cudaGetSymbolAddress((void**)&st,  g_st);

    cudaFuncSetAttribute(flash_mma_kernel,
                         cudaFuncAttributeMaxDynamicSharedMemorySize, SMEM_FL);
    cudaFuncSetAttribute(qkv_proj_kernel,
                         cudaFuncAttributeMaxDynamicSharedMemorySize, SMEM_PJ);

    gn_stats_kernel<<<BATCH * G, 256>>>(x, st);
    pwcvt_kernel<<<16, 1024>>>(p_w, pwb);

    qkv_proj_kernel<<<dim3(NN / 128, BATCH), 256, SMEM_PJ>>>(
        q_w, q_b, k_w, k_b, v_w, v_b, gn_w, gn_b, st, x, qt, kt, v);

    flash_mma_kernel<<<BATCH * 32, 256, SMEM_FL>>>(qt, kt, v, pwb, p_b, x, out);
}